// round 12
// baseline (speedup 1.0000x reference)
#include <cuda_runtime.h>
#include <cuda_fp16.h>
#include <cstdint>
#include <math.h>

// ---------------- problem constants ----------------
#define S_TOK   1024
#define HID     768
#define NE      64
#define TK      8
#define CAPMAX  256
#define I1      3072
#define I2      6144

// ---------------- GEMM tiling (fp16 operands) ----------------
#define BM   128
#define BK   32                        // k elements per chunk
#define PRB  80                        // bytes per smem row (40 halves, conflict-free)
#define A_BYTES (BM * PRB)             // 10240
#define B_BYTES (128 * PRB)            // 10240
#define STG     (A_BYTES + B_BYTES)    // 20480
#define NSTAGE  4
#define SMEM_BYTES (NSTAGE * STG)      // 81920
#define NC1 (HID / BK)                 // 24
#define NC2 (I1 / BK)                  // 96

// merged-grid sizes
#define G1_EXP_BLKS (48 * 2 * NE)      // 6144
#define G1_SH_BLKS  (48 * 8)           // 384
#define G2_EXP_BLKS (6 * 2 * NE)       // 768
#define G2_SH_BLKS  (6 * 8)            // 48

// ---------------- device scratch ----------------
__device__ __align__(16)  float g_topw[S_TOK][TK];
__device__ __align__(16)  int   g_topi[S_TOK][TK];
__device__ __align__(16)  int   g_slot[S_TOK][TK];
__device__ __align__(16)  int   g_ecount[NE];
__device__ __align__(16)  int   g_etok[NE][CAPMAX];
__device__ __align__(256) __half g_xh[S_TOK][HID];            // fp16 X
__device__ __align__(256) __half g_sh_gated[S_TOK][I1];       // fp16 gated
__device__ __align__(256) __half g_ex_gated[NE][CAPMAX][I1];  // fp16 gated
__device__ __align__(256) float  g_ex_out[NE][CAPMAX][HID];

// ---------------- helpers ----------------
__device__ __forceinline__ uint32_t smem_u32(const void* p) {
    uint32_t a;
    asm("{ .reg .u64 t; cvta.to.shared.u64 t, %1; cvt.u32.u64 %0, t; }" : "=r"(a) : "l"(p));
    return a;
}
__device__ __forceinline__ uint32_t lds_u32(uint32_t addr) {
    uint32_t v;
    asm volatile("ld.shared.b32 %0, [%1];" : "=r"(v) : "r"(addr));
    return v;
}
// pack two floats to half2 (lo=x, hi=y)
__device__ __forceinline__ uint32_t f2h2(float x, float y) {
    uint32_t v;
    asm("cvt.rn.f16x2.f32 %0, %1, %2;" : "=r"(v) : "f"(y), "f"(x));
    return v;
}
// cvt float4 -> 4 halves, store 8B to smem
__device__ __forceinline__ void cvt_sts_h(uint32_t addr, float4 v) {
    uint32_t p0 = f2h2(v.x, v.y);
    uint32_t p1 = f2h2(v.z, v.w);
    asm volatile("st.shared.v2.b32 [%0], {%1, %2};" :: "r"(addr), "r"(p0), "r"(p1) : "memory");
}
// async 16B copy gmem->smem; pred=0 zero-fills
__device__ __forceinline__ void cpa16(uint32_t dst, const void* src, int pred) {
    int sz = pred ? 16 : 0;
    asm volatile("cp.async.cg.shared.global [%0], [%1], 16, %2;"
                 :: "r"(dst), "l"(src), "r"(sz) : "memory");
}
#define CP_COMMIT() asm volatile("cp.async.commit_group;" ::: "memory")
#define CP_WAIT2()  asm volatile("cp.async.wait_group 2;" ::: "memory")

#define MMA_F16(c, a, b0v, b1v) \
    asm volatile("mma.sync.aligned.m16n8k16.row.col.f32.f16.f16.f32 " \
        "{%0,%1,%2,%3}, {%4,%5,%6,%7}, {%8,%9}, {%0,%1,%2,%3};" \
        : "+f"((c)[0]), "+f"((c)[1]), "+f"((c)[2]), "+f"((c)[3]) \
        : "r"((a)[0]), "r"((a)[1]), "r"((a)[2]), "r"((a)[3]), "r"(b0v), "r"(b1v))

extern __shared__ char dsm[];

// ---------------- X -> fp16 ----------------
__global__ void round_x_kernel(const float* __restrict__ x) {
    int i = (blockIdx.x * 256 + threadIdx.x) * 4;
    float4 v = *(const float4*)(x + i);
    uint2 o;
    o.x = f2h2(v.x, v.y);
    o.y = f2h2(v.z, v.w);
    *(uint2*)(&g_xh[0][0] + i) = o;
}

// ---------------- gating (exact fp32) ----------------
__global__ void gating_kernel(const float* __restrict__ x,
                              const float* __restrict__ wg) {
    int s = blockIdx.x;
    __shared__ float xs[HID];
    __shared__ float logits_s[NE];
    int tid = threadIdx.x;

    for (int i = tid; i < HID; i += 256) xs[i] = x[(size_t)s * HID + i];
    __syncthreads();

    int e = tid >> 2, sub = tid & 3;
    const float* w = wg + (size_t)e * HID;
    float acc = 0.f;
    for (int i = sub; i < HID; i += 4) acc += xs[i] * w[i];
    acc += __shfl_down_sync(0xffffffffu, acc, 2);
    acc += __shfl_down_sync(0xffffffffu, acc, 1);
    if (sub == 0) logits_s[e] = acc;
    __syncthreads();

    if (tid < 32) {
        float v0 = logits_s[tid];
        float v1 = logits_s[tid + 32];
        float tv[TK]; int tix[TK];
#pragma unroll
        for (int r = 0; r < TK; r++) {
            float bv; int bi;
            if (v0 >= v1) { bv = v0; bi = tid; }
            else          { bv = v1; bi = tid + 32; }
#pragma unroll
            for (int off = 16; off > 0; off >>= 1) {
                float ov = __shfl_down_sync(0xffffffffu, bv, off);
                int   oi = __shfl_down_sync(0xffffffffu, bi, off);
                if (ov > bv || (ov == bv && oi < bi)) { bv = ov; bi = oi; }
            }
            bv = __shfl_sync(0xffffffffu, bv, 0);
            bi = __shfl_sync(0xffffffffu, bi, 0);
            if (bi == tid)      v0 = -INFINITY;
            if (bi == tid + 32) v1 = -INFINITY;
            tv[r] = bv; tix[r] = bi;
        }
        if (tid == 0) {
            float m = tv[0], wv[TK], D = 0.f;
#pragma unroll
            for (int r = 0; r < TK; r++) { wv[r] = expf(tv[r] - m); D += wv[r]; }
            D = fmaxf(D, 1.1920929e-7f);
#pragma unroll
            for (int r = 0; r < TK; r++) { g_topw[s][r] = wv[r] / D; g_topi[s][r] = tix[r]; }
        }
    }
}

// ---------------- priority ----------------
__global__ void priority_kernel(const int* __restrict__ capacity) {
    int e = blockIdx.x, lane = threadIdx.x;
    int cap = capacity[0];
    if (cap > CAPMAX) cap = CAPMAX;
    if (cap < 0) cap = 0;

    int offset = 0;
    for (int base = 0; base < S_TOK * TK; base += 32) {
        int p = base + lane;
        int k = p / S_TOK;
        int s = p - k * S_TOK;
        bool match = (g_topi[s][k] == e);
        unsigned mask = __ballot_sync(0xffffffffu, match);
        if (match) {
            int c = offset + __popc(mask & ((1u << lane) - 1u));
            if (c < cap) { g_slot[s][k] = c; g_etok[e][c] = s; }
            else         { g_slot[s][k] = -1; }
        }
        offset += __popc(mask);
    }
    if (lane == 0) g_ecount[e] = (offset < cap) ? offset : cap;
}

// ---------------- GEMM1 (fp16 mma, 4-stage cp.async A) + SwiGLU ----------------
__global__ __launch_bounds__(256, 2)
void gemm1_mma(const float* __restrict__ Wsh,
               const float* __restrict__ Wex) {
    int b = blockIdx.x;
    int M, x, y; const int* gather; const float* Wp; __half* Out;
    if (b < G1_EXP_BLKS) {
        int e   = b / 96;
        int rem = b - e * 96;
        y = rem / 48; x = rem - y * 48;
        M = g_ecount[e]; gather = g_etok[e];
        Wp = Wex + (size_t)e * I2 * HID; Out = &g_ex_gated[e][0][0];
    } else {
        int b2 = b - G1_EXP_BLKS;
        y = b2 / 48; x = b2 - y * 48;
        M = S_TOK; gather = nullptr; Wp = Wsh; Out = &g_sh_gated[0][0];
    }
    int m0 = y * BM;
    if (m0 >= M) return;
    int n0 = x * 64;
    int Mrem = M - m0; if (Mrem > BM) Mrem = BM;
    int ntiles = (Mrem + 15) >> 4;
    int npass64 = (ntiles * 16 + 63) >> 6;

    uint32_t sb = smem_u32(dsm);
    int t = threadIdx.x, lane = t & 31, wid = t >> 5;
    int wm = wid >> 2, wn = wid & 3;
    int lq = lane >> 2, lr = lane & 3;

    // A loader: 16B per thread, 64 rows/pass, 2 passes
    int kseg = t & 3;
    int r64  = t >> 2;
    const __half* ap[2]; int apred[2];
#pragma unroll
    for (int p = 0; p < 2; p++) {
        int m = m0 + p * 64 + r64;
        apred[p] = (p < npass64 && m < M);
        int mm = apred[p] ? (gather ? gather[m] : m) : 0;
        ap[p] = &g_xh[0][0] + (size_t)mm * HID + kseg * 8;
    }
    uint32_t aoff[2];
#pragma unroll
    for (int p = 0; p < 2; p++) aoff[p] = (uint32_t)((p * 64 + r64) * PRB + kseg * 16);

    // B loader: float4 per thread, 32 rows/pass, 4 passes
    int kseg8 = t & 7;
    int r32   = t >> 3;
    const float* bp[4];
#pragma unroll
    for (int p = 0; p < 4; p++) {
        int row = p * 32 + r32;
        int wr = (row < 64) ? (n0 + row) : (n0 + row - 64 + I1);
        bp[p] = Wp + (size_t)wr * HID + kseg8 * 4;
    }
    uint32_t boff[4];
#pragma unroll
    for (int p = 0; p < 4; p++) boff[p] = (uint32_t)(A_BYTES + (p * 32 + r32) * PRB + kseg8 * 8);

    float acc1[4][2][4], acc2[4][2][4];
#pragma unroll
    for (int mt = 0; mt < 4; mt++)
#pragma unroll
        for (int nt = 0; nt < 2; nt++)
#pragma unroll
            for (int i = 0; i < 4; i++) { acc1[mt][nt][i] = 0.f; acc2[mt][nt][i] = 0.f; }

    float4 vbr[4];
    // prologue: A chunks 0..2 as 3 groups; B chunk 0 sync
#pragma unroll
    for (int c = 0; c < 3; c++) {
        if (c < NC1) {
            uint32_t Sb = sb + c * STG;
            int koh = c * BK;
#pragma unroll
            for (int p = 0; p < 2; p++) cpa16(Sb + aoff[p], ap[p] + koh, apred[p]);
        }
        CP_COMMIT();
    }
#pragma unroll
    for (int p = 0; p < 4; p++) vbr[p] = *(const float4*)(bp[p]);
#pragma unroll
    for (int p = 0; p < 4; p++) cvt_sts_h(sb + boff[p], vbr[p]);
    CP_WAIT2();
    __syncthreads();

#pragma unroll 1
    for (int kc = 0; kc < NC1; kc++) {
        int buf = kc & (NSTAGE - 1);
        // issue A(kc+3)
        if (kc + 3 < NC1) {
            uint32_t Sb = sb + ((kc + 3) & (NSTAGE - 1)) * STG;
            int koh = (kc + 3) * BK;
#pragma unroll
            for (int p = 0; p < 2; p++) cpa16(Sb + aoff[p], ap[p] + koh, apred[p]);
        }
        CP_COMMIT();
        // B prefetch LDG for kc+1
        if (kc + 1 < NC1) {
            int kof = (kc + 1) * BK;
#pragma unroll
            for (int p = 0; p < 4; p++) vbr[p] = *(const float4*)(bp[p] + kof);
        }
        uint32_t Ab = sb + buf * STG;
        uint32_t Bb = Ab + A_BYTES;
#pragma unroll
        for (int ks = 0; ks < 2; ks++) {
            uint32_t kcol = (uint32_t)((ks * 8 + lr) * 4);
            uint32_t b1v[2][2], b2v[2][2];
#pragma unroll
            for (int nt = 0; nt < 2; nt++) {
                uint32_t base1 = Bb + (uint32_t)((wn * 16 + nt * 8 + lq) * PRB) + kcol;
                b1v[nt][0] = lds_u32(base1);
                b1v[nt][1] = lds_u32(base1 + 16);
                uint32_t base2 = base1 + 64 * PRB;
                b2v[nt][0] = lds_u32(base2);
                b2v[nt][1] = lds_u32(base2 + 16);
            }
#pragma unroll
            for (int mt = 0; mt < 4; mt++) {
                int ti = mt * 2 + wm;
                if (ti < ntiles) {
                    uint32_t a[4];
                    uint32_t base = Ab + (uint32_t)((ti * 16 + lq) * PRB) + kcol;
                    a[0] = lds_u32(base);
                    a[1] = lds_u32(base + 8 * PRB);
                    a[2] = lds_u32(base + 16);
                    a[3] = lds_u32(base + 8 * PRB + 16);
#pragma unroll
                    for (int nt = 0; nt < 2; nt++) {
                        MMA_F16(acc1[mt][nt], a, b1v[nt][0], b1v[nt][1]);
                        MMA_F16(acc2[mt][nt], a, b2v[nt][0], b2v[nt][1]);
                    }
                }
            }
        }
        if (kc + 1 < NC1) {
            uint32_t S2 = sb + ((kc + 1) & (NSTAGE - 1)) * STG;
#pragma unroll
            for (int p = 0; p < 4; p++) cvt_sts_h(S2 + boff[p], vbr[p]);
        }
        CP_WAIT2();
        __syncthreads();
    }

    // epilogue: fused SwiGLU -> fp16 output
#pragma unroll
    for (int mt = 0; mt < 4; mt++) {
        int ti = mt * 2 + wm;
        if (ti >= ntiles) continue;
        int rbase = m0 + ti * 16 + lq;
#pragma unroll
        for (int nt = 0; nt < 2; nt++) {
            int col = n0 + wn * 16 + nt * 8 + lr * 2;
#pragma unroll
            for (int half = 0; half < 2; half++) {
                int r = rbase + half * 8;
                if (r < M) {
                    float g1a = acc1[mt][nt][half * 2 + 0];
                    float g1b = acc1[mt][nt][half * 2 + 1];
                    float g2a = acc2[mt][nt][half * 2 + 0];
                    float g2b = acc2[mt][nt][half * 2 + 1];
                    float oa = g1a * (g2a / (1.f + expf(-g2a)));
                    float ob = g1b * (g2b / (1.f + expf(-g2b)));
                    *(uint32_t*)&Out[(size_t)r * I1 + col] = f2h2(oa, ob);
                }
            }
        }
    }
}

// ---------------- GEMM2 (fp16 mma, 4-stage cp.async A): 128 x 128 ----------------
__global__ __launch_bounds__(256, 2)
void gemm2_mma(const float* __restrict__ Wsh,
               const float* __restrict__ Wex,
               float* __restrict__ dout) {
    int b = blockIdx.x;
    int M, x, y; const __half* G; const float* Wp; float* Out;
    if (b < G2_EXP_BLKS) {
        int e   = b / 12;
        int rem = b - e * 12;
        y = rem / 6; x = rem - y * 6;
        M = g_ecount[e]; G = &g_ex_gated[e][0][0];
        Wp = Wex + (size_t)e * HID * I1; Out = &g_ex_out[e][0][0];
    } else {
        int b2 = b - G2_EXP_BLKS;
        y = b2 / 6; x = b2 - y * 6;
        M = S_TOK; G = &g_sh_gated[0][0]; Wp = Wsh; Out = dout;
    }
    int m0 = y * BM;
    if (m0 >= M) return;
    int n0 = x * 128;
    int Mrem = M - m0; if (Mrem > BM) Mrem = BM;
    int ntiles = (Mrem + 15) >> 4;
    int npass64 = (ntiles * 16 + 63) >> 6;

    uint32_t sb = smem_u32(dsm);
    int t = threadIdx.x, lane = t & 31, wid = t >> 5;
    int wm = wid >> 2, wn = wid & 3;
    int lq = lane >> 2, lr = lane & 3;

    int kseg = t & 3;
    int r64  = t >> 2;
    const __half* ap[2]; int apred[2];
#pragma unroll
    for (int p = 0; p < 2; p++) {
        int m = m0 + p * 64 + r64;
        apred[p] = (p < npass64 && m < M);
        int mm = apred[p] ? m : 0;
        ap[p] = G + (size_t)mm * I1 + kseg * 8;
    }
    uint32_t aoff[2];
#pragma unroll
    for (int p = 0; p < 2; p++) aoff[p] = (uint32_t)((p * 64 + r64) * PRB + kseg * 16);

    int kseg8 = t & 7;
    int r32   = t >> 3;
    const float* bp[4];
#pragma unroll
    for (int p = 0; p < 4; p++)
        bp[p] = Wp + (size_t)(n0 + p * 32 + r32) * I1 + kseg8 * 4;
    uint32_t boff[4];
#pragma unroll
    for (int p = 0; p < 4; p++) boff[p] = (uint32_t)(A_BYTES + (p * 32 + r32) * PRB + kseg8 * 8);

    float acc[4][4][4];
#pragma unroll
    for (int mt = 0; mt < 4; mt++)
#pragma unroll
        for (int nt = 0; nt < 4; nt++)
#pragma unroll
            for (int i = 0; i < 4; i++) acc[mt][nt][i] = 0.f;

    float4 vbr[4];
#pragma unroll
    for (int c = 0; c < 3; c++) {
        if (c < NC2) {
            uint32_t Sb = sb + c * STG;
            int koh = c * BK;
#pragma unroll
            for (int p = 0; p < 2; p++) cpa16(Sb + aoff[p], ap[p] + koh, apred[p]);
        }
        CP_COMMIT();
    }
#pragma unroll
    for (int p = 0; p < 4; p++) vbr[p] = *(const float4*)(bp[p]);
#pragma unroll
    for (int p = 0; p < 4; p++) cvt_sts_h(sb + boff[p], vbr[p]);
    CP_WAIT2();
    __syncthreads();

#pragma unroll 1
    for (int kc = 0; kc < NC2; kc++) {
        int buf = kc & (NSTAGE - 1);
        if (kc + 3 < NC2) {
            uint32_t Sb = sb + ((kc + 3) & (NSTAGE - 1)) * STG;
            int koh = (kc + 3) * BK;
#pragma unroll
            for (int p = 0; p < 2; p++) cpa16(Sb + aoff[p], ap[p] + koh, apred[p]);
        }
        CP_COMMIT();
        if (kc + 1 < NC2) {
            int kof = (kc + 1) * BK;
#pragma unroll
            for (int p = 0; p < 4; p++) vbr[p] = *(const float4*)(bp[p] + kof);
        }
        uint32_t Ab = sb + buf * STG;
        uint32_t Bb = Ab + A_BYTES;
#pragma unroll
        for (int ks = 0; ks < 2; ks++) {
            uint32_t kcol = (uint32_t)((ks * 8 + lr) * 4);
            uint32_t bv[4][2];
#pragma unroll
            for (int nt = 0; nt < 4; nt++) {
                uint32_t base = Bb + (uint32_t)((wn * 32 + nt * 8 + lq) * PRB) + kcol;
                bv[nt][0] = lds_u32(base);
                bv[nt][1] = lds_u32(base + 16);
            }
#pragma unroll
            for (int mt = 0; mt < 4; mt++) {
                int ti = mt * 2 + wm;
                if (ti < ntiles) {
                    uint32_t a[4];
                    uint32_t base = Ab + (uint32_t)((ti * 16 + lq) * PRB) + kcol;
                    a[0] = lds_u32(base);
                    a[1] = lds_u32(base + 8 * PRB);
                    a[2] = lds_u32(base + 16);
                    a[3] = lds_u32(base + 8 * PRB + 16);
#pragma unroll
                    for (int nt = 0; nt < 4; nt++)
                        MMA_F16(acc[mt][nt], a, bv[nt][0], bv[nt][1]);
                }
            }
        }
        if (kc + 1 < NC2) {
            uint32_t S2 = sb + ((kc + 1) & (NSTAGE - 1)) * STG;
#pragma unroll
            for (int p = 0; p < 4; p++) cvt_sts_h(S2 + boff[p], vbr[p]);
        }
        CP_WAIT2();
        __syncthreads();
    }

#pragma unroll
    for (int mt = 0; mt < 4; mt++) {
        int ti = mt * 2 + wm;
        if (ti >= ntiles) continue;
        int rbase = m0 + ti * 16 + lq;
#pragma unroll
        for (int nt = 0; nt < 4; nt++) {
            int col = n0 + wn * 32 + nt * 8 + lr * 2;
#pragma unroll
            for (int half = 0; half < 2; half++) {
                int r = rbase + half * 8;
                if (r < M) {
                    float2 o;
                    o.x = acc[mt][nt][half * 2 + 0];
                    o.y = acc[mt][nt][half * 2 + 1];
                    *(float2*)&Out[(size_t)r * HID + col] = o;
                }
            }
        }
    }
}

// ---------------- combine ----------------
__global__ void combine_kernel(float* __restrict__ out) {
    int s = blockIdx.x, tid = threadIdx.x;
    __shared__ int ke[TK], kc_[TK];
    __shared__ float kw[TK];
    if (tid < TK) { ke[tid] = g_topi[s][tid]; kc_[tid] = g_slot[s][tid]; kw[tid] = g_topw[s][tid]; }
    __syncthreads();
    for (int h = tid; h < HID; h += 256) {
        float acc = out[(size_t)s * HID + h];
#pragma unroll
        for (int k = 0; k < TK; k++) {
            int c = kc_[k];
            if (c >= 0) acc += kw[k] * g_ex_out[ke[k]][c][h];
        }
        out[(size_t)s * HID + h] = acc;
    }
}

// ---------------------------------------------------------------------------
extern "C" void kernel_launch(void* const* d_in, const int* in_sizes, int n_in,
                              void* d_out, int out_size) {
    const float* x      = (const float*)d_in[0];
    const float* w_gu   = (const float*)d_in[1];
    const float* w_down = (const float*)d_in[2];
    const float* wg     = (const float*)d_in[3];
    const float* w1     = (const float*)d_in[4];
    const float* w2     = (const float*)d_in[5];
    const int*   cap    = (const int*)d_in[6];
    float* out = (float*)d_out;

    cudaFuncSetAttribute(gemm1_mma, cudaFuncAttributeMaxDynamicSharedMemorySize, SMEM_BYTES);
    cudaFuncSetAttribute(gemm2_mma, cudaFuncAttributeMaxDynamicSharedMemorySize, SMEM_BYTES);

    gating_kernel<<<S_TOK, 256>>>(x, wg);
    round_x_kernel<<<S_TOK * HID / 1024, 256>>>(x);
    priority_kernel<<<NE, 32>>>(cap);

    gemm1_mma<<<G1_EXP_BLKS + G1_SH_BLKS, 256, SMEM_BYTES>>>(w_gu, w1);
    gemm2_mma<<<G2_EXP_BLKS + G2_SH_BLKS, 256, SMEM_BYTES>>>(w_down, w2, out);

    combine_kernel<<<S_TOK, 256>>>(out);
}

// round 13
// speedup vs baseline: 1.1338x; 1.1338x over previous
#include <cuda_runtime.h>
#include <cuda_fp16.h>
#include <cstdint>
#include <math.h>

// ---------------- problem constants ----------------
#define S_TOK   1024
#define HID     768
#define NE      64
#define TK      8
#define CAPMAX  256
#define I1      3072
#define I2      6144

// ---------------- GEMM tiling ----------------
#define BM   128
#define BK   32                        // k elements per chunk
#define PRA  80                        // A smem row bytes (fp16, 40 halves)
#define PRB2 160                       // B smem row bytes (fp32, 40 floats)
#define A_BYTES (BM * PRA)             // 10240
#define B_BYTES (128 * PRB2)           // 20480
#define STG     (A_BYTES + B_BYTES)    // 30720
#define NSTAGE  3
#define SMEM_BYTES (NSTAGE * STG)      // 92160
#define NC1 (HID / BK)                 // 24
#define NC2 (I1 / BK)                  // 96

// merged-grid sizes
#define G1_EXP_BLKS (48 * 2 * NE)      // 6144
#define G1_SH_BLKS  (48 * 8)           // 384
#define G2_EXP_BLKS (6 * 2 * NE)       // 768
#define G2_SH_BLKS  (6 * 8)            // 48

// ---------------- device scratch ----------------
__device__ __align__(16)  float g_topw[S_TOK][TK];
__device__ __align__(16)  int   g_topi[S_TOK][TK];
__device__ __align__(16)  int   g_slot[S_TOK][TK];
__device__ __align__(16)  int   g_ecount[NE];
__device__ __align__(16)  int   g_etok[NE][CAPMAX];
__device__ __align__(256) __half g_xh[S_TOK][HID];            // fp16 X
__device__ __align__(256) __half g_sh_gated[S_TOK][I1];       // fp16 gated
__device__ __align__(256) __half g_ex_gated[NE][CAPMAX][I1];  // fp16 gated
__device__ __align__(256) float  g_ex_out[NE][CAPMAX][HID];

// ---------------- helpers ----------------
__device__ __forceinline__ uint32_t smem_u32(const void* p) {
    uint32_t a;
    asm("{ .reg .u64 t; cvta.to.shared.u64 t, %1; cvt.u32.u64 %0, t; }" : "=r"(a) : "l"(p));
    return a;
}
__device__ __forceinline__ uint32_t lds_u32(uint32_t addr) {
    uint32_t v;
    asm volatile("ld.shared.b32 %0, [%1];" : "=r"(v) : "r"(addr));
    return v;
}
// pack two floats to half2 (lo=x, hi=y)
__device__ __forceinline__ uint32_t f2h2(float x, float y) {
    uint32_t v;
    asm("cvt.rn.f16x2.f32 %0, %1, %2;" : "=r"(v) : "f"(y), "f"(x));
    return v;
}
// load 2 fp32 from smem, convert to half2
__device__ __forceinline__ uint32_t lds2_cvt(uint32_t addr) {
    float fx, fy;
    asm volatile("ld.shared.v2.f32 {%0, %1}, [%2];" : "=f"(fx), "=f"(fy) : "r"(addr));
    return f2h2(fx, fy);
}
// async 16B copy gmem->smem; pred=0 zero-fills
__device__ __forceinline__ void cpa16(uint32_t dst, const void* src, int pred) {
    int sz = pred ? 16 : 0;
    asm volatile("cp.async.cg.shared.global [%0], [%1], 16, %2;"
                 :: "r"(dst), "l"(src), "r"(sz) : "memory");
}
#define CP_COMMIT() asm volatile("cp.async.commit_group;" ::: "memory")
#define CP_WAIT1()  asm volatile("cp.async.wait_group 1;" ::: "memory")

#define MMA_F16(c, a, b0v, b1v) \
    asm volatile("mma.sync.aligned.m16n8k16.row.col.f32.f16.f16.f32 " \
        "{%0,%1,%2,%3}, {%4,%5,%6,%7}, {%8,%9}, {%0,%1,%2,%3};" \
        : "+f"((c)[0]), "+f"((c)[1]), "+f"((c)[2]), "+f"((c)[3]) \
        : "r"((a)[0]), "r"((a)[1]), "r"((a)[2]), "r"((a)[3]), "r"(b0v), "r"(b1v))

extern __shared__ char dsm[];

// ---------------- X -> fp16 ----------------
__global__ void round_x_kernel(const float* __restrict__ x) {
    int i = (blockIdx.x * 256 + threadIdx.x) * 4;
    float4 v = *(const float4*)(x + i);
    uint2 o;
    o.x = f2h2(v.x, v.y);
    o.y = f2h2(v.z, v.w);
    *(uint2*)(&g_xh[0][0] + i) = o;
}

// ---------------- gating (exact fp32) ----------------
__global__ void gating_kernel(const float* __restrict__ x,
                              const float* __restrict__ wg) {
    int s = blockIdx.x;
    __shared__ float xs[HID];
    __shared__ float logits_s[NE];
    int tid = threadIdx.x;

    for (int i = tid; i < HID; i += 256) xs[i] = x[(size_t)s * HID + i];
    __syncthreads();

    int e = tid >> 2, sub = tid & 3;
    const float* w = wg + (size_t)e * HID;
    float acc = 0.f;
    for (int i = sub; i < HID; i += 4) acc += xs[i] * w[i];
    acc += __shfl_down_sync(0xffffffffu, acc, 2);
    acc += __shfl_down_sync(0xffffffffu, acc, 1);
    if (sub == 0) logits_s[e] = acc;
    __syncthreads();

    if (tid < 32) {
        float v0 = logits_s[tid];
        float v1 = logits_s[tid + 32];
        float tv[TK]; int tix[TK];
#pragma unroll
        for (int r = 0; r < TK; r++) {
            float bv; int bi;
            if (v0 >= v1) { bv = v0; bi = tid; }
            else          { bv = v1; bi = tid + 32; }
#pragma unroll
            for (int off = 16; off > 0; off >>= 1) {
                float ov = __shfl_down_sync(0xffffffffu, bv, off);
                int   oi = __shfl_down_sync(0xffffffffu, bi, off);
                if (ov > bv || (ov == bv && oi < bi)) { bv = ov; bi = oi; }
            }
            bv = __shfl_sync(0xffffffffu, bv, 0);
            bi = __shfl_sync(0xffffffffu, bi, 0);
            if (bi == tid)      v0 = -INFINITY;
            if (bi == tid + 32) v1 = -INFINITY;
            tv[r] = bv; tix[r] = bi;
        }
        if (tid == 0) {
            float m = tv[0], wv[TK], D = 0.f;
#pragma unroll
            for (int r = 0; r < TK; r++) { wv[r] = expf(tv[r] - m); D += wv[r]; }
            D = fmaxf(D, 1.1920929e-7f);
#pragma unroll
            for (int r = 0; r < TK; r++) { g_topw[s][r] = wv[r] / D; g_topi[s][r] = tix[r]; }
        }
    }
}

// ---------------- priority ----------------
__global__ void priority_kernel(const int* __restrict__ capacity) {
    int e = blockIdx.x, lane = threadIdx.x;
    int cap = capacity[0];
    if (cap > CAPMAX) cap = CAPMAX;
    if (cap < 0) cap = 0;

    int offset = 0;
    for (int base = 0; base < S_TOK * TK; base += 32) {
        int p = base + lane;
        int k = p / S_TOK;
        int s = p - k * S_TOK;
        bool match = (g_topi[s][k] == e);
        unsigned mask = __ballot_sync(0xffffffffu, match);
        if (match) {
            int c = offset + __popc(mask & ((1u << lane) - 1u));
            if (c < cap) { g_slot[s][k] = c; g_etok[e][c] = s; }
            else         { g_slot[s][k] = -1; }
        }
        offset += __popc(mask);
    }
    if (lane == 0) g_ecount[e] = (offset < cap) ? offset : cap;
}

// ---------------- GEMM1 (fp16 mma, A+B cp.async 3-stage) + SwiGLU ----------------
__global__ __launch_bounds__(256, 2)
void gemm1_mma(const float* __restrict__ Wsh,
               const float* __restrict__ Wex) {
    int b = blockIdx.x;
    int M, x, y; const int* gather; const float* Wp; __half* Out;
    if (b < G1_EXP_BLKS) {
        int e   = b / 96;
        int rem = b - e * 96;
        y = rem / 48; x = rem - y * 48;
        M = g_ecount[e]; gather = g_etok[e];
        Wp = Wex + (size_t)e * I2 * HID; Out = &g_ex_gated[e][0][0];
    } else {
        int b2 = b - G1_EXP_BLKS;
        y = b2 / 48; x = b2 - y * 48;
        M = S_TOK; gather = nullptr; Wp = Wsh; Out = &g_sh_gated[0][0];
    }
    int m0 = y * BM;
    if (m0 >= M) return;
    int n0 = x * 64;
    int Mrem = M - m0; if (Mrem > BM) Mrem = BM;
    int ntiles = (Mrem + 15) >> 4;
    int npass64 = (ntiles * 16 + 63) >> 6;

    uint32_t sb = smem_u32(dsm);
    int t = threadIdx.x, lane = t & 31, wid = t >> 5;
    int wm = wid >> 2, wn = wid & 3;
    int lq = lane >> 2, lr = lane & 3;

    // A loader: 16B per thread, 64 rows/pass, 2 passes
    int kseg = t & 3;
    int r64  = t >> 2;
    const __half* ap[2]; int apred[2];
#pragma unroll
    for (int p = 0; p < 2; p++) {
        int m = m0 + p * 64 + r64;
        apred[p] = (p < npass64 && m < M);
        int mm = apred[p] ? (gather ? gather[m] : m) : 0;
        ap[p] = &g_xh[0][0] + (size_t)mm * HID + kseg * 8;
    }
    uint32_t aoff[2];
#pragma unroll
    for (int p = 0; p < 2; p++) aoff[p] = (uint32_t)((p * 64 + r64) * PRA + kseg * 16);

    // B loader (fp32): 16B per thread, 32 rows/pass, 4 passes
    int kseg8 = t & 7;
    int r32   = t >> 3;
    const float* bp[4];
#pragma unroll
    for (int p = 0; p < 4; p++) {
        int row = p * 32 + r32;
        int wr = (row < 64) ? (n0 + row) : (n0 + row - 64 + I1);
        bp[p] = Wp + (size_t)wr * HID + kseg8 * 4;
    }
    uint32_t boff[4];
#pragma unroll
    for (int p = 0; p < 4; p++) boff[p] = (uint32_t)(A_BYTES + (p * 32 + r32) * PRB2 + kseg8 * 16);

    float acc1[4][2][4], acc2[4][2][4];
#pragma unroll
    for (int mt = 0; mt < 4; mt++)
#pragma unroll
        for (int nt = 0; nt < 2; nt++)
#pragma unroll
            for (int i = 0; i < 4; i++) { acc1[mt][nt][i] = 0.f; acc2[mt][nt][i] = 0.f; }

    // prologue: issue chunks 0 and 1
#pragma unroll
    for (int c = 0; c < 2; c++) {
        uint32_t Sb = sb + c * STG;
        int ko = c * BK;   // halves for A, floats for B (both 32/chunk)
#pragma unroll
        for (int p = 0; p < 2; p++) cpa16(Sb + aoff[p], ap[p] + ko, apred[p]);
#pragma unroll
        for (int p = 0; p < 4; p++) cpa16(Sb + boff[p], bp[p] + ko, 1);
        CP_COMMIT();
    }
    CP_WAIT1();
    __syncthreads();

    int buf = 0;
#pragma unroll 1
    for (int kc = 0; kc < NC1; kc++) {
        uint32_t Ab = sb + buf * STG;
        uint32_t Bb = Ab + A_BYTES;
#pragma unroll
        for (int ks = 0; ks < 2; ks++) {
            // fp32 B: col byte = (ks*16 + 2*lr)*4
            uint32_t kcolB = (uint32_t)(ks * 64 + lr * 8);
            uint32_t kcolA = (uint32_t)((ks * 8 + lr) * 4);
            uint32_t b1v[2][2], b2v[2][2];
#pragma unroll
            for (int nt = 0; nt < 2; nt++) {
                uint32_t base1 = Bb + (uint32_t)((wn * 16 + nt * 8 + lq) * PRB2) + kcolB;
                b1v[nt][0] = lds2_cvt(base1);
                b1v[nt][1] = lds2_cvt(base1 + 32);
                uint32_t base2 = base1 + 64 * PRB2;
                b2v[nt][0] = lds2_cvt(base2);
                b2v[nt][1] = lds2_cvt(base2 + 32);
            }
#pragma unroll
            for (int mt = 0; mt < 4; mt++) {
                int ti = mt * 2 + wm;
                if (ti < ntiles) {
                    uint32_t a[4];
                    uint32_t base = Ab + (uint32_t)((ti * 16 + lq) * PRA) + kcolA;
                    a[0] = lds_u32(base);
                    a[1] = lds_u32(base + 8 * PRA);
                    a[2] = lds_u32(base + 16);
                    a[3] = lds_u32(base + 8 * PRA + 16);
#pragma unroll
                    for (int nt = 0; nt < 2; nt++) {
                        MMA_F16(acc1[mt][nt], a, b1v[nt][0], b1v[nt][1]);
                        MMA_F16(acc2[mt][nt], a, b2v[nt][0], b2v[nt][1]);
                    }
                }
            }
        }
        // issue chunk kc+2
        if (kc + 2 < NC1) {
            int nb = buf + 2; if (nb >= NSTAGE) nb -= NSTAGE;
            uint32_t Sb = sb + nb * STG;
            int ko = (kc + 2) * BK;
#pragma unroll
            for (int p = 0; p < 2; p++) cpa16(Sb + aoff[p], ap[p] + ko, apred[p]);
#pragma unroll
            for (int p = 0; p < 4; p++) cpa16(Sb + boff[p], bp[p] + ko, 1);
        }
        CP_COMMIT();
        CP_WAIT1();
        __syncthreads();
        if (++buf == NSTAGE) buf = 0;
    }

    // epilogue: fused SwiGLU -> fp16 output
#pragma unroll
    for (int mt = 0; mt < 4; mt++) {
        int ti = mt * 2 + wm;
        if (ti >= ntiles) continue;
        int rbase = m0 + ti * 16 + lq;
#pragma unroll
        for (int nt = 0; nt < 2; nt++) {
            int col = n0 + wn * 16 + nt * 8 + lr * 2;
#pragma unroll
            for (int half = 0; half < 2; half++) {
                int r = rbase + half * 8;
                if (r < M) {
                    float g1a = acc1[mt][nt][half * 2 + 0];
                    float g1b = acc1[mt][nt][half * 2 + 1];
                    float g2a = acc2[mt][nt][half * 2 + 0];
                    float g2b = acc2[mt][nt][half * 2 + 1];
                    float oa = g1a * (g2a / (1.f + expf(-g2a)));
                    float ob = g1b * (g2b / (1.f + expf(-g2b)));
                    *(uint32_t*)&Out[(size_t)r * I1 + col] = f2h2(oa, ob);
                }
            }
        }
    }
}

// ---------------- GEMM2 (fp16 mma, A+B cp.async 3-stage): 128 x 128 ----------------
__global__ __launch_bounds__(256, 2)
void gemm2_mma(const float* __restrict__ Wsh,
               const float* __restrict__ Wex,
               float* __restrict__ dout) {
    int b = blockIdx.x;
    int M, x, y; const __half* G; const float* Wp; float* Out;
    if (b < G2_EXP_BLKS) {
        int e   = b / 12;
        int rem = b - e * 12;
        y = rem / 6; x = rem - y * 6;
        M = g_ecount[e]; G = &g_ex_gated[e][0][0];
        Wp = Wex + (size_t)e * HID * I1; Out = &g_ex_out[e][0][0];
    } else {
        int b2 = b - G2_EXP_BLKS;
        y = b2 / 6; x = b2 - y * 6;
        M = S_TOK; G = &g_sh_gated[0][0]; Wp = Wsh; Out = dout;
    }
    int m0 = y * BM;
    if (m0 >= M) return;
    int n0 = x * 128;
    int Mrem = M - m0; if (Mrem > BM) Mrem = BM;
    int ntiles = (Mrem + 15) >> 4;
    int npass64 = (ntiles * 16 + 63) >> 6;

    uint32_t sb = smem_u32(dsm);
    int t = threadIdx.x, lane = t & 31, wid = t >> 5;
    int wm = wid >> 2, wn = wid & 3;
    int lq = lane >> 2, lr = lane & 3;

    int kseg = t & 3;
    int r64  = t >> 2;
    const __half* ap[2]; int apred[2];
#pragma unroll
    for (int p = 0; p < 2; p++) {
        int m = m0 + p * 64 + r64;
        apred[p] = (p < npass64 && m < M);
        int mm = apred[p] ? m : 0;
        ap[p] = G + (size_t)mm * I1 + kseg * 8;
    }
    uint32_t aoff[2];
#pragma unroll
    for (int p = 0; p < 2; p++) aoff[p] = (uint32_t)((p * 64 + r64) * PRA + kseg * 16);

    int kseg8 = t & 7;
    int r32   = t >> 3;
    const float* bp[4];
#pragma unroll
    for (int p = 0; p < 4; p++)
        bp[p] = Wp + (size_t)(n0 + p * 32 + r32) * I1 + kseg8 * 4;
    uint32_t boff[4];
#pragma unroll
    for (int p = 0; p < 4; p++) boff[p] = (uint32_t)(A_BYTES + (p * 32 + r32) * PRB2 + kseg8 * 16);

    float acc[4][4][4];
#pragma unroll
    for (int mt = 0; mt < 4; mt++)
#pragma unroll
        for (int nt = 0; nt < 4; nt++)
#pragma unroll
            for (int i = 0; i < 4; i++) acc[mt][nt][i] = 0.f;

#pragma unroll
    for (int c = 0; c < 2; c++) {
        uint32_t Sb = sb + c * STG;
        int ko = c * BK;
#pragma unroll
        for (int p = 0; p < 2; p++) cpa16(Sb + aoff[p], ap[p] + ko, apred[p]);
#pragma unroll
        for (int p = 0; p < 4; p++) cpa16(Sb + boff[p], bp[p] + ko, 1);
        CP_COMMIT();
    }
    CP_WAIT1();
    __syncthreads();

    int buf = 0;
#pragma unroll 1
    for (int kc = 0; kc < NC2; kc++) {
        uint32_t Ab = sb + buf * STG;
        uint32_t Bb = Ab + A_BYTES;
#pragma unroll
        for (int ks = 0; ks < 2; ks++) {
            uint32_t kcolB = (uint32_t)(ks * 64 + lr * 8);
            uint32_t kcolA = (uint32_t)((ks * 8 + lr) * 4);
            uint32_t bv[4][2];
#pragma unroll
            for (int nt = 0; nt < 4; nt++) {
                uint32_t base = Bb + (uint32_t)((wn * 32 + nt * 8 + lq) * PRB2) + kcolB;
                bv[nt][0] = lds2_cvt(base);
                bv[nt][1] = lds2_cvt(base + 32);
            }
#pragma unroll
            for (int mt = 0; mt < 4; mt++) {
                int ti = mt * 2 + wm;
                if (ti < ntiles) {
                    uint32_t a[4];
                    uint32_t base = Ab + (uint32_t)((ti * 16 + lq) * PRA) + kcolA;
                    a[0] = lds_u32(base);
                    a[1] = lds_u32(base + 8 * PRA);
                    a[2] = lds_u32(base + 16);
                    a[3] = lds_u32(base + 8 * PRA + 16);
#pragma unroll
                    for (int nt = 0; nt < 4; nt++)
                        MMA_F16(acc[mt][nt], a, bv[nt][0], bv[nt][1]);
                }
            }
        }
        if (kc + 2 < NC2) {
            int nb = buf + 2; if (nb >= NSTAGE) nb -= NSTAGE;
            uint32_t Sb = sb + nb * STG;
            int ko = (kc + 2) * BK;
#pragma unroll
            for (int p = 0; p < 2; p++) cpa16(Sb + aoff[p], ap[p] + ko, apred[p]);
#pragma unroll
            for (int p = 0; p < 4; p++) cpa16(Sb + boff[p], bp[p] + ko, 1);
        }
        CP_COMMIT();
        CP_WAIT1();
        __syncthreads();
        if (++buf == NSTAGE) buf = 0;
    }

#pragma unroll
    for (int mt = 0; mt < 4; mt++) {
        int ti = mt * 2 + wm;
        if (ti >= ntiles) continue;
        int rbase = m0 + ti * 16 + lq;
#pragma unroll
        for (int nt = 0; nt < 4; nt++) {
            int col = n0 + wn * 32 + nt * 8 + lr * 2;
#pragma unroll
            for (int half = 0; half < 2; half++) {
                int r = rbase + half * 8;
                if (r < M) {
                    float2 o;
                    o.x = acc[mt][nt][half * 2 + 0];
                    o.y = acc[mt][nt][half * 2 + 1];
                    *(float2*)&Out[(size_t)r * HID + col] = o;
                }
            }
        }
    }
}

// ---------------- combine ----------------
__global__ void combine_kernel(float* __restrict__ out) {
    int s = blockIdx.x, tid = threadIdx.x;
    __shared__ int ke[TK], kc_[TK];
    __shared__ float kw[TK];
    if (tid < TK) { ke[tid] = g_topi[s][tid]; kc_[tid] = g_slot[s][tid]; kw[tid] = g_topw[s][tid]; }
    __syncthreads();
    for (int h = tid; h < HID; h += 256) {
        float acc = out[(size_t)s * HID + h];
#pragma unroll
        for (int k = 0; k < TK; k++) {
            int c = kc_[k];
            if (c >= 0) acc += kw[k] * g_ex_out[ke[k]][c][h];
        }
        out[(size_t)s * HID + h] = acc;
    }
}

// ---------------------------------------------------------------------------
extern "C" void kernel_launch(void* const* d_in, const int* in_sizes, int n_in,
                              void* d_out, int out_size) {
    const float* x      = (const float*)d_in[0];
    const float* w_gu   = (const float*)d_in[1];
    const float* w_down = (const float*)d_in[2];
    const float* wg     = (const float*)d_in[3];
    const float* w1     = (const float*)d_in[4];
    const float* w2     = (const float*)d_in[5];
    const int*   cap    = (const int*)d_in[6];
    float* out = (float*)d_out;

    cudaFuncSetAttribute(gemm1_mma, cudaFuncAttributeMaxDynamicSharedMemorySize, SMEM_BYTES);
    cudaFuncSetAttribute(gemm2_mma, cudaFuncAttributeMaxDynamicSharedMemorySize, SMEM_BYTES);

    gating_kernel<<<S_TOK, 256>>>(x, wg);
    round_x_kernel<<<S_TOK * HID / 1024, 256>>>(x);
    priority_kernel<<<NE, 32>>>(cap);

    gemm1_mma<<<G1_EXP_BLKS + G1_SH_BLKS, 256, SMEM_BYTES>>>(w_gu, w1);
    gemm2_mma<<<G2_EXP_BLKS + G2_SH_BLKS, 256, SMEM_BYTES>>>(w_down, w2, out);

    combine_kernel<<<S_TOK, 256>>>(out);
}